// round 10
// baseline (speedup 1.0000x reference)
#include <cuda_runtime.h>

#define EMB 64
#define NSEG_MAX 4097
#define THREADS 256

__device__ float g_wvo[EMB];     // w_value @ w_out
__device__ float g_c;            // b_value.w_out + b_out
__device__ float g_b0;           // b_out[0]
__device__ int   g_starts[NSEG_MAX];

// Kernel 1: segment-bounds scan over sorted ids + fused-head precompute.
__global__ __launch_bounds__(THREADS)
void bounds_kernel(const int*   __restrict__ ids,
                   const float* __restrict__ w_value,
                   const float* __restrict__ b_value,
                   const float* __restrict__ w_out,
                   const float* __restrict__ b_out,
                   int Btot, int Nimg) {
    const int tid = threadIdx.x;
    const int i   = blockIdx.x * THREADS + tid;

    if (blockIdx.x == 0 && tid < EMB) {
        float s = 0.f;
#pragma unroll
        for (int h = 0; h < EMB; ++h)
            s = fmaf(__ldg(w_value + tid * EMB + h), __ldg(w_out + h), s);
        g_wvo[tid] = s;
        if (tid == 0) {
            float c = 0.f;
            for (int h = 0; h < EMB; ++h) c = fmaf(__ldg(b_value + h), __ldg(w_out + h), c);
            g_c  = c + __ldg(b_out);
            g_b0 = __ldg(b_out);
        }
    }

    if (i < Btot) {
        const int cur = __ldg(ids + i);
        if (i == 0) {
            for (int j = 0; j <= cur; ++j) g_starts[j] = 0;
        } else {
            const int prev = __ldg(ids + i - 1);
            for (int j = prev + 1; j <= cur; ++j) g_starts[j] = i;
        }
        if (i == Btot - 1) {
            for (int j = cur + 1; j <= Nimg; ++j) g_starts[j] = Btot;
        }
    }
}

// Kernel 2: one warp = one CTA = one segment. Software-pipelined: the next
// 16-row block's 8 LDG.128 are issued BEFORE computing the current block
// (static A/B double buffer), so loads stay in flight through the compute
// phase. Score partial reduced over the 16-lane row group (4 shfls); exp
// replicated; value partials reduced once per segment.
__global__ __launch_bounds__(32)
void pool_kernel(const float* __restrict__ emb,
                 const float* __restrict__ w_attn,
                 float* __restrict__ out,
                 int Btot, int Nimg) {
    const int n    = blockIdx.x;            // segment id
    const int lane = threadIdx.x;
    const int grp  = lane & 15;             // column slice [4*grp, 4*grp+4)
    const int half = lane >> 4;             // row slot 0/1

    const float4 wa = reinterpret_cast<const float4*>(w_attn)[grp];
    const float4 wv = reinterpret_cast<const float4*>(g_wvo)[grp];

    const int start = g_starts[n];
    const int end   = g_starts[n + 1];
    const int cnt   = end - start;

    float se0 = 0.f, sev0 = 0.f, se1 = 0.f, sev1 = 0.f;
    float se2 = 0.f, sev2 = 0.f, se3 = 0.f, sev3 = 0.f;

    const float4* const pbase = reinterpret_cast<const float4*>(emb) + grp;

// load 16 rows starting at row-base _b into buffer (8 x LDG.128, evict-first)
#define LOADB(buf, _b) do {                                                    \
    const float4* _p = pbase + ((size_t)((_b) + half) << 4);                   \
    _Pragma("unroll")                                                          \
    for (int u = 0; u < 8; ++u) (buf)[u] = __ldcs(_p + (u << 5));              \
} while (0)

#define COMPUTE(buf) do {                                                      \
    _Pragma("unroll")                                                          \
    for (int u = 0; u < 8; ++u) {                                              \
        float sp = (buf)[u].x * wa.x + (buf)[u].y * wa.y +                     \
                   (buf)[u].z * wa.z + (buf)[u].w * wa.w;                      \
        float vp = (buf)[u].x * wv.x + (buf)[u].y * wv.y +                     \
                   (buf)[u].z * wv.z + (buf)[u].w * wv.w;                      \
        _Pragma("unroll")                                                      \
        for (int o = 8; o; o >>= 1) sp += __shfl_xor_sync(0xffffffffu, sp, o); \
        const float ex = __expf(sp);        /* replicated on 16-lane group */  \
        if      ((u & 3) == 0) { se0 += ex; sev0 = fmaf(ex, vp, sev0); }       \
        else if ((u & 3) == 1) { se1 += ex; sev1 = fmaf(ex, vp, sev1); }       \
        else if ((u & 3) == 2) { se2 += ex; sev2 = fmaf(ex, vp, sev2); }       \
        else                   { se3 += ex; sev3 = fmaf(ex, vp, sev3); }       \
    }                                                                          \
} while (0)

    const int nblk = cnt >> 4;              // full 16-row blocks
    float4 A[8], Bf[8];
    int base = start, b = 0;

    if (nblk > 0) LOADB(A, base);
    while (b + 2 <= nblk) {
        LOADB(Bf, base + 16);               // prefetch next block
        COMPUTE(A);
        if (b + 3 <= nblk) LOADB(A, base + 32);
        COMPUTE(Bf);
        base += 32; b += 2;
    }
    if (b < nblk) { COMPUTE(A); base += 16; }

    // ---- masked tail (up to 15 rows) ----
    const int mid = start + (nblk << 4);
    if (mid < end) {
#pragma unroll
        for (int u = 0; u < 8; ++u) {
            const int row = mid + u * 2 + half;
            const bool v = row < end;
            float4 e = make_float4(0.f, 0.f, 0.f, 0.f);
            if (v) e = __ldcs(pbase + ((size_t)row << 4));
            float sp = e.x * wa.x + e.y * wa.y + e.z * wa.z + e.w * wa.w;
            float vp = e.x * wv.x + e.y * wv.y + e.z * wv.z + e.w * wv.w;
#pragma unroll
            for (int o = 8; o; o >>= 1) sp += __shfl_xor_sync(0xffffffffu, sp, o);
            const float ex = v ? __expf(sp) : 0.f;
            se0 += ex; sev0 = fmaf(ex, vp, sev0);
        }
    }
#undef LOADB
#undef COMPUTE

    // ---- once-per-segment reduction (intra-warp only) ----
    float se  = (se0 + se1) + (se2 + se3);       // replicated within 16-group
    float sev = (sev0 + sev1) + (sev2 + sev3);
    se += __shfl_xor_sync(0xffffffffu, se, 16);
#pragma unroll
    for (int o = 16; o; o >>= 1) sev += __shfl_xor_sync(0xffffffffu, sev, o);

    const float r = (cnt == 0) ? g_b0 : (sev / se + g_c);   // replicated

    if (lane == 0) {
        out[Btot + n]        = r;          // r_images
        out[Btot + Nimg + n] = (float)n;   // unique_ids
    }
    for (int i = start + lane; i < end; i += 32) out[i] = r;   // r_reflections
}

extern "C" void kernel_launch(void* const* d_in, const int* in_sizes, int n_in,
                              void* d_out, int out_size) {
    const float* emb     = (const float*)d_in[0];
    const int*   ids     = (const int*)  d_in[1];
    const float* w_attn  = (const float*)d_in[2];
    // d_in[3] = b_attn: cancels under softmax shift invariance
    const float* w_value = (const float*)d_in[4];
    const float* b_value = (const float*)d_in[5];
    const float* w_out   = (const float*)d_in[6];
    const float* b_out   = (const float*)d_in[7];
    float* out = (float*)d_out;

    const int Btot = in_sizes[0] / EMB;          // 1048576
    const int Nimg = (out_size - Btot) / 2;      // 4096

    bounds_kernel<<<(Btot + THREADS - 1) / THREADS, THREADS>>>(
        ids, w_value, b_value, w_out, b_out, Btot, Nimg);
    pool_kernel<<<Nimg, 32>>>(emb, w_attn, out, Btot, Nimg);
}

// round 11
// speedup vs baseline: 1.0889x; 1.0889x over previous
#include <cuda_runtime.h>

#define EMB 64
#define NSEG_MAX 4097
#define THREADS 256

__device__ float g_wvo[EMB];     // w_value @ w_out
__device__ float g_c;            // b_value.w_out + b_out
__device__ float g_b0;           // b_out[0]
__device__ int   g_starts[NSEG_MAX];

// Kernel 1: segment-bounds scan over sorted ids + fused-head precompute.
__global__ __launch_bounds__(THREADS)
void bounds_kernel(const int*   __restrict__ ids,
                   const float* __restrict__ w_value,
                   const float* __restrict__ b_value,
                   const float* __restrict__ w_out,
                   const float* __restrict__ b_out,
                   int Btot, int Nimg) {
    const int tid = threadIdx.x;
    const int i   = blockIdx.x * THREADS + tid;

    if (blockIdx.x == 0 && tid < EMB) {
        float s = 0.f;
#pragma unroll
        for (int h = 0; h < EMB; ++h)
            s = fmaf(__ldg(w_value + tid * EMB + h), __ldg(w_out + h), s);
        g_wvo[tid] = s;
        if (tid == 0) {
            float c = 0.f;
            for (int h = 0; h < EMB; ++h) c = fmaf(__ldg(b_value + h), __ldg(w_out + h), c);
            g_c  = c + __ldg(b_out);
            g_b0 = __ldg(b_out);
        }
    }

    if (i < Btot) {
        const int cur = __ldg(ids + i);
        if (i == 0) {
            for (int j = 0; j <= cur; ++j) g_starts[j] = 0;
        } else {
            const int prev = __ldg(ids + i - 1);
            for (int j = prev + 1; j <= cur; ++j) g_starts[j] = i;
        }
        if (i == Btot - 1) {
            for (int j = cur + 1; j <= Nimg; ++j) g_starts[j] = Btot;
        }
    }
}

// Kernel 2: one warp = one CTA = one segment. Straight-line 12-way unrolled
// loop (24 rows / 12 front-batched LDG.128 per iteration) — simple body so
// ptxas software-pipelines it. 16 lanes/row; score partial shfl-reduced per
// row; exp replicated; value partials reduced once per segment. No smem.
__global__ __launch_bounds__(32)
void pool_kernel(const float* __restrict__ emb,
                 const float* __restrict__ w_attn,
                 float* __restrict__ out,
                 int Btot, int Nimg) {
    const int n    = blockIdx.x;            // segment id
    const int lane = threadIdx.x;
    const int grp  = lane & 15;             // column slice [4*grp, 4*grp+4)
    const int half = lane >> 4;             // row slot 0/1

    const float4 wa = reinterpret_cast<const float4*>(w_attn)[grp];
    const float4 wv = reinterpret_cast<const float4*>(g_wvo)[grp];

    const int start = g_starts[n];
    const int end   = g_starts[n + 1];
    const int cnt   = end - start;

    float se0 = 0.f, sev0 = 0.f, se1 = 0.f, sev1 = 0.f;
    float se2 = 0.f, sev2 = 0.f, se3 = 0.f, sev3 = 0.f;

    const float4* const pbase = reinterpret_cast<const float4*>(emb) + grp;

    const int nfull = cnt - cnt % 24;       // rows in unpredicated blocks
    const int mid   = start + nfull;

    // ---- main loop: 12 independent LDG.128 (evict-first) front-batched ----
    for (int base = start; base < mid; base += 24) {
        float4 e[12];
#pragma unroll
        for (int u = 0; u < 12; ++u)
            e[u] = __ldcs(pbase + ((size_t)(base + u * 2 + half) << 4));
#pragma unroll
        for (int u = 0; u < 12; ++u) {
            float sp = e[u].x * wa.x + e[u].y * wa.y + e[u].z * wa.z + e[u].w * wa.w;
            float vp = e[u].x * wv.x + e[u].y * wv.y + e[u].z * wv.z + e[u].w * wv.w;
#pragma unroll
            for (int o = 8; o; o >>= 1) sp += __shfl_xor_sync(0xffffffffu, sp, o);
            const float ex = __expf(sp);            // replicated on the 16-lane group
            if      ((u & 3) == 0) { se0 += ex; sev0 = fmaf(ex, vp, sev0); }
            else if ((u & 3) == 1) { se1 += ex; sev1 = fmaf(ex, vp, sev1); }
            else if ((u & 3) == 2) { se2 += ex; sev2 = fmaf(ex, vp, sev2); }
            else                   { se3 += ex; sev3 = fmaf(ex, vp, sev3); }
        }
    }

    // ---- masked tail (up to 23 rows) ----
    if (mid < end) {
#pragma unroll
        for (int u = 0; u < 12; ++u) {
            const int row = mid + u * 2 + half;
            const bool v = row < end;
            float4 e = make_float4(0.f, 0.f, 0.f, 0.f);
            if (v) e = __ldcs(pbase + ((size_t)row << 4));
            float sp = e.x * wa.x + e.y * wa.y + e.z * wa.z + e.w * wa.w;
            float vp = e.x * wv.x + e.y * wv.y + e.z * wv.z + e.w * wv.w;
#pragma unroll
            for (int o = 8; o; o >>= 1) sp += __shfl_xor_sync(0xffffffffu, sp, o);
            const float ex = v ? __expf(sp) : 0.f;
            se0 += ex; sev0 = fmaf(ex, vp, sev0);
        }
    }

    // ---- once-per-segment reduction (intra-warp only) ----
    float se  = (se0 + se1) + (se2 + se3);       // replicated within 16-group
    float sev = (sev0 + sev1) + (sev2 + sev3);
    se += __shfl_xor_sync(0xffffffffu, se, 16);
#pragma unroll
    for (int o = 16; o; o >>= 1) sev += __shfl_xor_sync(0xffffffffu, sev, o);

    const float r = (cnt == 0) ? g_b0 : (sev / se + g_c);   // replicated

    if (lane == 0) {
        out[Btot + n]        = r;          // r_images
        out[Btot + Nimg + n] = (float)n;   // unique_ids
    }
    for (int i = start + lane; i < end; i += 32) out[i] = r;   // r_reflections
}

extern "C" void kernel_launch(void* const* d_in, const int* in_sizes, int n_in,
                              void* d_out, int out_size) {
    const float* emb     = (const float*)d_in[0];
    const int*   ids     = (const int*)  d_in[1];
    const float* w_attn  = (const float*)d_in[2];
    // d_in[3] = b_attn: cancels under softmax shift invariance
    const float* w_value = (const float*)d_in[4];
    const float* b_value = (const float*)d_in[5];
    const float* w_out   = (const float*)d_in[6];
    const float* b_out   = (const float*)d_in[7];
    float* out = (float*)d_out;

    const int Btot = in_sizes[0] / EMB;          // 1048576
    const int Nimg = (out_size - Btot) / 2;      // 4096

    bounds_kernel<<<(Btot + THREADS - 1) / THREADS, THREADS>>>(
        ids, w_value, b_value, w_out, b_out, Btot, Nimg);
    pool_kernel<<<Nimg, 32>>>(emb, w_attn, out, Btot, Nimg);
}